// round 4
// baseline (speedup 1.0000x reference)
#include <cuda_runtime.h>
#include <cstdint>
#include <math.h>

#define BATCH   2048
#define IN_DIM  512
#define NUM_OUT 256

#define BM 32
#define BN 64
#define BK 32
#define NTHREADS 128
#define NSTEPS (IN_DIM / BK)   // 16

typedef unsigned long long ull;

// Precomputed -sigmoid(5*W_raw), transposed to [k][o] and duplicated along o:
// g_wdup[k*512 + 2*o] == g_wdup[k*512 + 2*o + 1] == -sigmoid(5*W_raw[o][k])
__device__ float g_wdup[IN_DIM * NUM_OUT * 2];

// Coalesced: consecutive threads read consecutive k of one W row (float4),
// write 4 scattered float2 stores (fire-and-forget).
__global__ void precompute_kernel(const float* __restrict__ Wraw) {
    int i = blockIdx.x * blockDim.x + threadIdx.x;   // 0 .. 32767
    if (i < NUM_OUT * (IN_DIM / 4)) {
        int o  = i >> 7;          // 0..255
        int k4 = (i & 127) * 4;   // 0,4,...,508
        float4 v = *reinterpret_cast<const float4*>(&Wraw[o * IN_DIM + k4]);
        float w0 = 1.0f / (1.0f + __expf(-5.0f * v.x));
        float w1 = 1.0f / (1.0f + __expf(-5.0f * v.y));
        float w2 = 1.0f / (1.0f + __expf(-5.0f * v.z));
        float w3 = 1.0f / (1.0f + __expf(-5.0f * v.w));
        float2 p;
        p.x = -w0; p.y = -w0;
        *reinterpret_cast<float2*>(&g_wdup[(k4 + 0) * (2 * NUM_OUT) + 2 * o]) = p;
        p.x = -w1; p.y = -w1;
        *reinterpret_cast<float2*>(&g_wdup[(k4 + 1) * (2 * NUM_OUT) + 2 * o]) = p;
        p.x = -w2; p.y = -w2;
        *reinterpret_cast<float2*>(&g_wdup[(k4 + 2) * (2 * NUM_OUT) + 2 * o]) = p;
        p.x = -w3; p.y = -w3;
        *reinterpret_cast<float2*>(&g_wdup[(k4 + 3) * (2 * NUM_OUT) + 2 * o]) = p;
    }
}

__device__ __forceinline__ ull ffma2(ull a, ull b, ull c) {
    ull d;
    asm("fma.rn.f32x2 %0, %1, %2, %3;" : "=l"(d) : "l"(a), "l"(b), "l"(c));
    return d;
}
__device__ __forceinline__ ull fmul2(ull a, ull b) {
    ull d;
    asm("mul.rn.f32x2 %0, %1, %2;" : "=l"(d) : "l"(a), "l"(b));
    return d;
}
__device__ __forceinline__ void cp_async16(uint32_t smem, const void* gptr) {
    asm volatile("cp.async.cg.shared.global [%0], [%1], 16;" :: "r"(smem), "l"(gptr));
}

// 32(M) x 64(N) tile per CTA, full K=512, no split, no combine.
// Thread tile 4 rows x 4 cols; accumulator packs two M-rows per f32x2 reg.
// z = 1 + (-w) * (1 - x) = fma(nw, t, 1).
__global__ void __launch_bounds__(NTHREADS, 2)
logic_kernel(const float* __restrict__ x, float* __restrict__ out) {
    // xs rows padded to 36 floats (144B, 16B-aligned row stride)
    __shared__ __align__(16) float xs[2][BK][36];
    // ws: duplicated -w tile: row k holds 128 floats = 64 cols duplicated (512B)
    __shared__ __align__(16) float ws[2][BK][2 * BN];

    const int tid = threadIdx.x;
    const int bm0 = blockIdx.x * BM;
    const int bn  = blockIdx.y;

    const int tc = tid & 15;   // 16 col-groups of 4 outputs
    const int tr = tid >> 4;   // 8 row-groups of 4 rows

    // x staging: row xm (0..31), k-quarter xq (8 k's each)
    const int xm = tid & 31;
    const int xq = tid >> 5;   // 0..3

    const ull ONE2 = 0x3F8000003F800000ULL;   // (1.0f, 1.0f)
    ull acc[2][4];
#pragma unroll
    for (int i = 0; i < 2; ++i)
#pragma unroll
        for (int j = 0; j < 4; ++j) acc[i][j] = ONE2;

    const float* xrow = x + (ull)(bm0 + xm) * IN_DIM + xq * 8;

    // ---------------- prologue: fill buffer 0 ----------------
    {
        float4 a = *reinterpret_cast<const float4*>(xrow + 0);
        float4 b = *reinterpret_cast<const float4*>(xrow + 4);
        // w tile stage 0: 32 rows x 512B = 1024 x 16B chunks, 8 per thread
#pragma unroll
        for (int c = 0; c < 8; ++c) {
            int idx = c * 128 + tid;
            int k   = idx >> 5;        // 0..31
            int col = idx & 31;        // 16B chunk within row
            const float* src = g_wdup + (ull)k * (2 * NUM_OUT) + bn * (2 * BN) + col * 4;
            cp_async16((uint32_t)__cvta_generic_to_shared(&ws[0][k][col * 4]), src);
        }
        asm volatile("cp.async.commit_group;" ::: "memory");
        int kb = xq * 8;
        xs[0][kb + 0][xm] = 1.0f - a.x;
        xs[0][kb + 1][xm] = 1.0f - a.y;
        xs[0][kb + 2][xm] = 1.0f - a.z;
        xs[0][kb + 3][xm] = 1.0f - a.w;
        xs[0][kb + 4][xm] = 1.0f - b.x;
        xs[0][kb + 5][xm] = 1.0f - b.y;
        xs[0][kb + 6][xm] = 1.0f - b.z;
        xs[0][kb + 7][xm] = 1.0f - b.w;
    }

    // ---------------- main loop ----------------
    for (int step = 0; step < NSTEPS; ++step) {
        const int buf  = step & 1;
        const int nbuf = buf ^ 1;
        const bool more = (step + 1 < NSTEPS);

        __syncthreads();   // compute(step-1) done; x STS(step) visible

        float4 a, b;
        if (more) {
            const float* xp = xrow + (step + 1) * BK;
            a = *reinterpret_cast<const float4*>(xp + 0);
            b = *reinterpret_cast<const float4*>(xp + 4);
            int k0 = (step + 1) * BK;
#pragma unroll
            for (int c = 0; c < 8; ++c) {
                int idx = c * 128 + tid;
                int k   = idx >> 5;
                int col = idx & 31;
                const float* src = g_wdup + (ull)(k0 + k) * (2 * NUM_OUT) + bn * (2 * BN) + col * 4;
                cp_async16((uint32_t)__cvta_generic_to_shared(&ws[nbuf][k][col * 4]), src);
            }
        }
        asm volatile("cp.async.commit_group;" ::: "memory");
        asm volatile("cp.async.wait_group 1;" ::: "memory");
        __syncthreads();   // ws[buf] fully landed

        // ---------- compute on buf ----------
#pragma unroll
        for (int k = 0; k < BK; ++k) {
            ulonglong2 xp = *reinterpret_cast<const ulonglong2*>(&xs[buf][k][tr * 4]);
            ulonglong2 wa = *reinterpret_cast<const ulonglong2*>(&ws[buf][k][tc * 8]);
            ulonglong2 wb = *reinterpret_cast<const ulonglong2*>(&ws[buf][k][tc * 8 + 4]);
            ull xv[2] = {xp.x, xp.y};               // row-pairs (tr*4+0,1), (tr*4+2,3)
            ull wv[4] = {wa.x, wa.y, wb.x, wb.y};   // (-w_j, -w_j) duplicated pairs
#pragma unroll
            for (int j = 0; j < 4; ++j) {
#pragma unroll
                for (int i = 0; i < 2; ++i) {
                    ull z = ffma2(wv[j], xv[i], ONE2);   // (1 - w*t, 1 - w*t)
                    acc[i][j] = fmul2(acc[i][j], z);
                }
            }
        }

        if (more) {
            int kb = xq * 8;
            xs[nbuf][kb + 0][xm] = 1.0f - a.x;
            xs[nbuf][kb + 1][xm] = 1.0f - a.y;
            xs[nbuf][kb + 2][xm] = 1.0f - a.z;
            xs[nbuf][kb + 3][xm] = 1.0f - a.w;
            xs[nbuf][kb + 4][xm] = 1.0f - b.x;
            xs[nbuf][kb + 5][xm] = 1.0f - b.y;
            xs[nbuf][kb + 6][xm] = 1.0f - b.z;
            xs[nbuf][kb + 7][xm] = 1.0f - b.w;
        }
    }

    // ---------------- epilogue: write final products ----------------
    float* orow = out + (ull)(bm0 + tr * 4) * NUM_OUT + bn * BN + tc * 4;
#pragma unroll
    for (int r = 0; r < 4; ++r) {
        int i = r >> 1;
        int h = r & 1;
        float4 v;
        v.x = __uint_as_float((unsigned)(acc[i][0] >> (h * 32)));
        v.y = __uint_as_float((unsigned)(acc[i][1] >> (h * 32)));
        v.z = __uint_as_float((unsigned)(acc[i][2] >> (h * 32)));
        v.w = __uint_as_float((unsigned)(acc[i][3] >> (h * 32)));
        *reinterpret_cast<float4*>(orow + (ull)r * NUM_OUT) = v;
    }
}

extern "C" void kernel_launch(void* const* d_in, const int* in_sizes, int n_in,
                              void* d_out, int out_size) {
    const float* x    = (const float*)d_in[0];   // [2048, 512]
    const float* Wraw = (const float*)d_in[1];   // [256, 512]
    float* out        = (float*)d_out;           // [2048, 256]

    precompute_kernel<<<(NUM_OUT * (IN_DIM / 4) + 127) / 128, 128>>>(Wraw);

    dim3 grid(BATCH / BM, NUM_OUT / BN);         // 64 x 4 = 256 CTAs
    logic_kernel<<<grid, NTHREADS>>>(x, out);
}